// round 2
// baseline (speedup 1.0000x reference)
#include <cuda_runtime.h>

// SegmentMM: out[i] = A[i] @ B_eff[segA[i]], A:[N,64] f32, B:[128,64,64] f32,
// segA:[N] int32 sorted, segB:[128] int32 (permutation labels for B).
// NOTE: jax without x64 downcasts int64 -> int32; harness delivers int32.
//
// Inputs (metadata order): d_in[0]=mat_A f32, d_in[1]=mat_B f32,
// d_in[2]=segment_id_A int32, d_in[3]=segment_id_B int32. Output f32 [N,64].

#define BR 128      // rows per block
#define BM 64       // M (full)
#define BK 64       // K (full)
#define APAD 68     // A smem row pitch (floats), mult of 4 for float4
#define BPAD 68     // B smem row pitch

#define S_SEG 128

__device__ int d_invB[S_SEG];   // inv[segB[j]] = j

__global__ void build_inv_kernel(const int* __restrict__ segB, int S) {
    int j = threadIdx.x;
    if (j < S) d_invB[segB[j]] = j;
}

__device__ __forceinline__ unsigned long long pack2(float x, float y) {
    unsigned long long r;
    asm("mov.b64 %0, {%1, %2};" : "=l"(r) : "f"(x), "f"(y));
    return r;
}
__device__ __forceinline__ void ffma2(unsigned long long& d,
                                      unsigned long long a,
                                      unsigned long long b) {
    asm("fma.rn.f32x2 %0, %1, %2, %0;" : "+l"(d) : "l"(a), "l"(b));
}
__device__ __forceinline__ float2 unpack2(unsigned long long v) {
    float2 f;
    asm("mov.b64 {%0, %1}, %2;" : "=f"(f.x), "=f"(f.y) : "l"(v));
    return f;
}

__global__ __launch_bounds__(256)
void segmm_kernel(const float* __restrict__ A,
                  const float* __restrict__ B,
                  const int* __restrict__ segA,
                  float* __restrict__ out)
{
    __shared__ float As[BR * APAD];   // row-major [r][k], padded
    __shared__ float Bs[BK * BPAD];   // [k][m], padded

    const int tid = threadIdx.x;
    const int tx  = tid & 15;         // column group: 4 cols each -> 64 cols
    const int ty  = tid >> 4;         // row group: 8 rows each -> 128 rows
    const int r0  = blockIdx.x * BR;
    const int row_base = ty * 8;
    const int col = tx * 4;

    // ---- load A tile (coalesced float4 global -> conflict-free smem) ----
    {
        const float4* A4 = (const float4*)(A + (size_t)r0 * BK);
        #pragma unroll
        for (int it = 0; it < (BR * BK / 4) / 256; ++it) {
            int i  = it * 256 + tid;
            int r  = i >> 4;          // row
            int kq = i & 15;          // float4 index along K
            *(float4*)(As + r * APAD + kq * 4) = A4[i];
        }
    }

    // per-thread segment ids for its 8 rows (int32, sorted)
    int myseg[8];
    #pragma unroll
    for (int r = 0; r < 8; ++r) myseg[r] = segA[r0 + row_base + r];

    const int s_lo = segA[r0];
    const int s_hi = segA[r0 + BR - 1];

    for (int s = s_lo; s <= s_hi; ++s) {
        // wait: previous pass's compute (reads Bs) done; also covers As fill
        __syncthreads();

        // ---- load B segment into smem ----
        {
            int j = d_invB[s];
            const float4* B4 = (const float4*)(B + (size_t)j * (BK * BM));
            #pragma unroll
            for (int it = 0; it < (BK * BM / 4) / 256; ++it) {
                int i  = it * 256 + tid;
                int k  = i >> 4;
                int mq = i & 15;
                *(float4*)(Bs + k * BPAD + mq * 4) = B4[i];
            }
        }
        __syncthreads();

        // does this thread own any row in segment s?
        bool any = false;
        #pragma unroll
        for (int r = 0; r < 8; ++r) any |= (myseg[r] == s);
        if (!any) continue;

        // ---- register-tile compute: 8 rows x 4 cols, f32x2 packed FMA ----
        unsigned long long acc[8][2];
        #pragma unroll
        for (int r = 0; r < 8; ++r) { acc[r][0] = 0ULL; acc[r][1] = 0ULL; }

        #pragma unroll 4
        for (int k4 = 0; k4 < BK / 4; ++k4) {
            float4 a4[8];
            #pragma unroll
            for (int r = 0; r < 8; ++r)
                a4[r] = *(const float4*)(As + (row_base + r) * APAD + k4 * 4);

            #pragma unroll
            for (int j = 0; j < 4; ++j) {
                float4 bv = *(const float4*)(Bs + (k4 * 4 + j) * BPAD + col);
                unsigned long long b01 = pack2(bv.x, bv.y);
                unsigned long long b23 = pack2(bv.z, bv.w);
                #pragma unroll
                for (int r = 0; r < 8; ++r) {
                    float av = (j == 0) ? a4[r].x :
                               (j == 1) ? a4[r].y :
                               (j == 2) ? a4[r].z : a4[r].w;
                    unsigned long long aa = pack2(av, av);
                    ffma2(acc[r][0], aa, b01);
                    ffma2(acc[r][1], aa, b23);
                }
            }
        }

        // ---- store rows belonging to segment s (coalesced float4) ----
        #pragma unroll
        for (int r = 0; r < 8; ++r) {
            if (myseg[r] == s) {
                float2 lo = unpack2(acc[r][0]);
                float2 hi = unpack2(acc[r][1]);
                *(float4*)(out + (size_t)(r0 + row_base + r) * BM + col)
                    = make_float4(lo.x, lo.y, hi.x, hi.y);
            }
        }
    }
}

extern "C" void kernel_launch(void* const* d_in, const int* in_sizes, int n_in,
                              void* d_out, int out_size) {
    const float* A    = (const float*)d_in[0];
    const float* B    = (const float*)d_in[1];
    const int*   segA = (const int*)d_in[2];
    const int*   segB = (const int*)d_in[3];
    float* out = (float*)d_out;

    const int N = in_sizes[0] / BK;      // 131072
    const int S = in_sizes[3];           // 128

    build_inv_kernel<<<1, S_SEG>>>(segB, S);
    segmm_kernel<<<N / BR, 256>>>(A, B, segA, out);
}

// round 4
// speedup vs baseline: 1.4286x; 1.4286x over previous
#include <cuda_runtime.h>
#include <cuda_bf16.h>
#include <cstdint>

// SegmentMM: out[i] = A[i] @ B_eff[segA[i]]
// A:[131072,64] f32, B:[128,64,64] f32, segA int32 sorted, segB int32 perm.
// Tensor path: bf16 3-split via mma.sync m16n8k16 (no 'a'-feature needed).

#define S_SEG 128
__device__ int d_invB[S_SEG];

__global__ void build_inv_kernel(const int* __restrict__ segB, int S) {
    int j = threadIdx.x;
    if (j < S) d_invB[segB[j]] = j;
}

// ---- smem layout (dynamic) ----
#define SM_AH 0          // 128 rows x 64 bf16, 128B/row, SW128   16KB
#define SM_AL 16384      //                                        16KB
#define SM_BH 32768      // 64 k-rows x 64 bf16, 128B/row, SW128    8KB
#define SM_BL 40960      //                                         8KB
#define SMEM_TOTAL 49152

__device__ __forceinline__ uint32_t smem_u32(const void* p) {
    uint32_t a;
    asm("{ .reg .u64 t; cvta.to.shared.u64 t, %1; cvt.u32.u64 %0, t; }"
        : "=r"(a) : "l"(p));
    return a;
}
__device__ __forceinline__ uint32_t sw128(uint32_t off) {
    return off ^ ((off >> 3) & 0x70);
}
__device__ __forceinline__ void ldsm_x4(uint32_t& r0, uint32_t& r1,
                                        uint32_t& r2, uint32_t& r3, uint32_t a) {
    asm volatile("ldmatrix.sync.aligned.m8n8.x4.shared.b16 {%0,%1,%2,%3}, [%4];"
                 : "=r"(r0), "=r"(r1), "=r"(r2), "=r"(r3) : "r"(a));
}
__device__ __forceinline__ void ldsm_x2t(uint32_t& r0, uint32_t& r1, uint32_t a) {
    asm volatile("ldmatrix.sync.aligned.m8n8.x2.trans.shared.b16 {%0,%1}, [%2];"
                 : "=r"(r0), "=r"(r1) : "r"(a));
}
__device__ __forceinline__ void mma16816(float* d, const uint32_t* a,
                                         uint32_t b0, uint32_t b1) {
    asm volatile(
        "mma.sync.aligned.m16n8k16.row.col.f32.bf16.bf16.f32 "
        "{%0,%1,%2,%3}, {%4,%5,%6,%7}, {%8,%9}, {%0,%1,%2,%3};"
        : "+f"(d[0]), "+f"(d[1]), "+f"(d[2]), "+f"(d[3])
        : "r"(a[0]), "r"(a[1]), "r"(a[2]), "r"(a[3]), "r"(b0), "r"(b1));
}

__device__ __forceinline__ void cvt_split4(float4 v, uint2& hi, uint2& lo) {
    __nv_bfloat162 h01 = __floats2bfloat162_rn(v.x, v.y);
    __nv_bfloat162 h23 = __floats2bfloat162_rn(v.z, v.w);
    float rx = v.x - __bfloat162float(h01.x);
    float ry = v.y - __bfloat162float(h01.y);
    float rz = v.z - __bfloat162float(h23.x);
    float rw = v.w - __bfloat162float(h23.y);
    __nv_bfloat162 l01 = __floats2bfloat162_rn(rx, ry);
    __nv_bfloat162 l23 = __floats2bfloat162_rn(rz, rw);
    hi = make_uint2(*(uint32_t*)&h01, *(uint32_t*)&h23);
    lo = make_uint2(*(uint32_t*)&l01, *(uint32_t*)&l23);
}

__global__ __launch_bounds__(256)
void segmm_hmma_kernel(const float* __restrict__ A,
                       const float* __restrict__ B,
                       const int* __restrict__ segA,
                       float* __restrict__ out)
{
    extern __shared__ char smem[];
    const uint32_t sb  = smem_u32(smem);
    const int tid  = threadIdx.x;
    const int w    = tid >> 5;          // warp 0..7, owns rows w*16..w*16+15
    const int lane = tid & 31;
    const int r0   = blockIdx.x * 128;

    // ---- convert A tile -> Ah/Al bf16 in SW128 smem ----
    {
        const float4* A4 = (const float4*)(A + (size_t)r0 * 64);
        #pragma unroll
        for (int it = 0; it < 8; ++it) {
            int i = it * 256 + tid;          // 0..2047 float4s
            float4 v = A4[i];
            int r = i >> 4, kq = i & 15;
            uint32_t sw = sw128((uint32_t)(r * 128 + kq * 8));
            uint2 hi, lo;
            cvt_split4(v, hi, lo);
            *(uint2*)(smem + SM_AH + sw) = hi;
            *(uint2*)(smem + SM_AL + sw) = lo;
        }
    }
    __syncthreads();

    // ---- load A fragments to registers (held for the whole kernel) ----
    // m16k16 tile per kstep: lanes 0-15 -> rows, lane>>4 -> k-halve chunk
    uint32_t ah[4][4], al[4][4];
    {
        uint32_t arow = (uint32_t)(w * 16 + (lane & 15));
        #pragma unroll
        for (int kk = 0; kk < 4; ++kk) {
            uint32_t off = arow * 128 + (uint32_t)(kk * 2 + (lane >> 4)) * 16;
            uint32_t sw  = sw128(off);
            ldsm_x4(ah[kk][0], ah[kk][1], ah[kk][2], ah[kk][3], sb + SM_AH + sw);
            ldsm_x4(al[kk][0], al[kk][1], al[kk][2], al[kk][3], sb + SM_AL + sw);
        }
    }

    // per-thread output rows (c-fragment layout) and their segments
    const int rA = w * 16 + (lane >> 2);
    const int rB = rA + 8;
    const int cb = (lane & 3) * 2;
    const int segLoRow = segA[r0 + rA];
    const int segHiRow = segA[r0 + rB];

    const int s_lo = segA[r0];
    const int s_hi = segA[r0 + 127];

    // B-fragment lane address component: row within 16-k tile
    const uint32_t brow_in = (uint32_t)(lane & 15);

    for (int s = s_lo; s <= s_hi; ++s) {
        __syncthreads();   // all warps done reading previous B tiles

        // ---- convert B segment -> Bh/Bl bf16 smem ----
        {
            int j = d_invB[s];
            const float4* B4 = (const float4*)(B + (size_t)j * 4096);
            #pragma unroll
            for (int it = 0; it < 4; ++it) {
                int i = it * 256 + tid;      // 0..1023 float4s
                float4 v = B4[i];
                int k = i >> 4, mq = i & 15;
                uint32_t sw = sw128((uint32_t)(k * 128 + mq * 8));
                uint2 hi, lo;
                cvt_split4(v, hi, lo);
                *(uint2*)(smem + SM_BH + sw) = hi;
                *(uint2*)(smem + SM_BL + sw) = lo;
            }
        }
        __syncthreads();

        // skip warps with no row in this segment
        bool okA = (segLoRow == s);
        bool okB = (segHiRow == s);
        if (__ballot_sync(0xffffffffu, okA || okB) == 0u) continue;

        // ---- compute: 8 ntiles x 4 ksteps x 3 mma ----
        float acc[8][4];
        #pragma unroll
        for (int nt = 0; nt < 8; ++nt)
            #pragma unroll
            for (int q = 0; q < 4; ++q) acc[nt][q] = 0.f;

        #pragma unroll
        for (int kk = 0; kk < 4; ++kk) {
            uint32_t roff = ((uint32_t)(kk * 16) + brow_in) * 128;
            #pragma unroll
            for (int nt = 0; nt < 8; ++nt) {
                uint32_t sw = sw128(roff + (uint32_t)nt * 16);
                uint32_t bh0, bh1, bl0, bl1;
                ldsm_x2t(bh0, bh1, sb + SM_BH + sw);
                ldsm_x2t(bl0, bl1, sb + SM_BL + sw);
                mma16816(acc[nt], ah[kk], bh0, bh1);
                mma16816(acc[nt], ah[kk], bl0, bl1);
                mma16816(acc[nt], al[kk], bh0, bh1);
            }
        }

        // ---- store rows belonging to segment s ----
        float* orA = out + (size_t)(r0 + rA) * 64 + cb;
        float* orB = out + (size_t)(r0 + rB) * 64 + cb;
        #pragma unroll
        for (int nt = 0; nt < 8; ++nt) {
            if (okA) *(float2*)(orA + nt * 8) = make_float2(acc[nt][0], acc[nt][1]);
            if (okB) *(float2*)(orB + nt * 8) = make_float2(acc[nt][2], acc[nt][3]);
        }
    }
}

extern "C" void kernel_launch(void* const* d_in, const int* in_sizes, int n_in,
                              void* d_out, int out_size) {
    const float* A    = (const float*)d_in[0];
    const float* B    = (const float*)d_in[1];
    const int*   segA = (const int*)d_in[2];
    const int*   segB = (const int*)d_in[3];
    float* out = (float*)d_out;

    const int N = in_sizes[0] / 64;      // 131072
    const int S = in_sizes[3];           // 128

    cudaFuncSetAttribute(segmm_hmma_kernel,
                         cudaFuncAttributeMaxDynamicSharedMemorySize, SMEM_TOTAL);

    build_inv_kernel<<<1, S_SEG>>>(segB, S);
    segmm_hmma_kernel<<<N / 128, 256, SMEM_TOTAL>>>(A, B, segA, out);
}

// round 5
// speedup vs baseline: 1.5878x; 1.1115x over previous
#include <cuda_runtime.h>
#include <cuda_bf16.h>
#include <cstdint>

// SegmentMM: out[i] = A[i] @ B_eff[segA[i]]
// A:[131072,64] f32, B:[128,64,64] f32, segA int32 sorted, segB int32 perm.
// bf16 3-split (Ah*Bh + Ah*Bl + Al*Bh) on HMMA m16n8k16.
// R5: B pre-split+pre-swizzled to global bf16 (per-label), cp.async copy in
// main kernel; 128-thr CTAs (64 rows) for 5 CTA/SM occupancy.

#define S_SEG 128

// Pre-split B, SW128-swizzled tile images, indexed by segment LABEL.
__device__ __align__(16) unsigned char d_Bh[S_SEG * 8192];
__device__ __align__(16) unsigned char d_Bl[S_SEG * 8192];

__device__ __forceinline__ uint32_t sw128(uint32_t off) {
    return off ^ ((off >> 3) & 0x70);
}

__device__ __forceinline__ void cvt_split4(float4 v, uint2& hi, uint2& lo) {
    __nv_bfloat162 h01 = __floats2bfloat162_rn(v.x, v.y);
    __nv_bfloat162 h23 = __floats2bfloat162_rn(v.z, v.w);
    float rx = v.x - __bfloat162float(h01.x);
    float ry = v.y - __bfloat162float(h01.y);
    float rz = v.z - __bfloat162float(h23.x);
    float rw = v.w - __bfloat162float(h23.y);
    __nv_bfloat162 l01 = __floats2bfloat162_rn(rx, ry);
    __nv_bfloat162 l23 = __floats2bfloat162_rn(rz, rw);
    hi = make_uint2(*(uint32_t*)&h01, *(uint32_t*)&h23);
    lo = make_uint2(*(uint32_t*)&l01, *(uint32_t*)&l23);
}

// ---- B pre-split kernel: block j converts B[j] -> d_Bh/d_Bl[segB[j]] ----
__global__ __launch_bounds__(256)
void presplit_B_kernel(const float* __restrict__ B,
                       const int* __restrict__ segB)
{
    const int j = blockIdx.x;
    const int s = segB[j];
    const int tid = threadIdx.x;
    const float4* B4 = (const float4*)(B + (size_t)j * 4096);
    unsigned char* bh = d_Bh + (size_t)s * 8192;
    unsigned char* bl = d_Bl + (size_t)s * 8192;
    #pragma unroll
    for (int it = 0; it < 4; ++it) {
        int i = it * 256 + tid;          // 0..1023 float4s
        float4 v = B4[i];
        int k = i >> 4, mq = i & 15;
        uint32_t sw = sw128((uint32_t)(k * 128 + mq * 8));
        uint2 hi, lo;
        cvt_split4(v, hi, lo);
        *(uint2*)(bh + sw) = hi;
        *(uint2*)(bl + sw) = lo;
    }
}

// ---- main kernel ----
#define SM_AH 0          // 64 rows x 64 bf16, 128B/row, SW128   8KB
#define SM_AL 8192       //                                       8KB
#define SM_BH 16384      // 64 k-rows x 64 bf16, SW128            8KB
#define SM_BL 24576      //                                       8KB
#define SMEM_TOTAL 32768

__device__ __forceinline__ uint32_t smem_u32(const void* p) {
    uint32_t a;
    asm("{ .reg .u64 t; cvta.to.shared.u64 t, %1; cvt.u32.u64 %0, t; }"
        : "=r"(a) : "l"(p));
    return a;
}
__device__ __forceinline__ void ldsm_x4(uint32_t& r0, uint32_t& r1,
                                        uint32_t& r2, uint32_t& r3, uint32_t a) {
    asm volatile("ldmatrix.sync.aligned.m8n8.x4.shared.b16 {%0,%1,%2,%3}, [%4];"
                 : "=r"(r0), "=r"(r1), "=r"(r2), "=r"(r3) : "r"(a));
}
__device__ __forceinline__ void ldsm_x2t(uint32_t& r0, uint32_t& r1, uint32_t a) {
    asm volatile("ldmatrix.sync.aligned.m8n8.x2.trans.shared.b16 {%0,%1}, [%2];"
                 : "=r"(r0), "=r"(r1) : "r"(a));
}
__device__ __forceinline__ void mma16816(float* d, const uint32_t* a,
                                         uint32_t b0, uint32_t b1) {
    asm volatile(
        "mma.sync.aligned.m16n8k16.row.col.f32.bf16.bf16.f32 "
        "{%0,%1,%2,%3}, {%4,%5,%6,%7}, {%8,%9}, {%0,%1,%2,%3};"
        : "+f"(d[0]), "+f"(d[1]), "+f"(d[2]), "+f"(d[3])
        : "r"(a[0]), "r"(a[1]), "r"(a[2]), "r"(a[3]), "r"(b0), "r"(b1));
}
#define CP_ASYNC16(dst, src)                                                   \
    asm volatile("cp.async.cg.shared.global [%0], [%1], 16;"                   \
                 :: "r"(dst), "l"(src) : "memory")
#define CP_COMMIT  asm volatile("cp.async.commit_group;" ::: "memory")
#define CP_WAIT0   asm volatile("cp.async.wait_group 0;" ::: "memory")

__global__ __launch_bounds__(128, 5)
void segmm_hmma_kernel(const float* __restrict__ A,
                       const int* __restrict__ segA,
                       float* __restrict__ out)
{
    __shared__ __align__(128) unsigned char smem[SMEM_TOTAL];
    const uint32_t sb  = smem_u32(smem);
    const int tid  = threadIdx.x;
    const int w    = tid >> 5;          // warp 0..3, owns rows w*16..w*16+15
    const int lane = tid & 31;
    const int r0   = blockIdx.x * 64;

    // ---- convert A tile (64x64 f32) -> Ah/Al bf16 SW128 smem ----
    {
        const float4* A4 = (const float4*)(A + (size_t)r0 * 64);
        #pragma unroll
        for (int it = 0; it < 8; ++it) {
            int i = it * 128 + tid;          // 0..1023 float4s
            float4 v = A4[i];
            int r = i >> 4, kq = i & 15;
            uint32_t sw = sw128((uint32_t)(r * 128 + kq * 8));
            uint2 hi, lo;
            cvt_split4(v, hi, lo);
            *(uint2*)(smem + SM_AH + sw) = hi;
            *(uint2*)(smem + SM_AL + sw) = lo;
        }
    }

    // per-thread output rows (c-fragment layout) and their segments
    const int rA = w * 16 + (lane >> 2);
    const int rB = rA + 8;
    const int cb = (lane & 3) * 2;
    const int segLoRow = segA[r0 + rA];
    const int segHiRow = segA[r0 + rB];
    const int s_lo = segA[r0];
    const int s_hi = segA[r0 + 63];

    const uint32_t brow_in = (uint32_t)(lane & 15);
    const uint32_t arow    = (uint32_t)(w * 16 + (lane & 15));
    const uint32_t acolsel = (uint32_t)(lane >> 4) * 16;

    for (int s = s_lo; s <= s_hi; ++s) {
        __syncthreads();   // prev pass done reading B smem (also covers A fill)

        // ---- cp.async copy pre-split B tile images ----
        {
            const unsigned char* gh = d_Bh + (size_t)s * 8192;
            const unsigned char* gl = d_Bl + (size_t)s * 8192;
            #pragma unroll
            for (int it = 0; it < 4; ++it) {
                uint32_t off = (uint32_t)(it * 128 + tid) * 16;
                CP_ASYNC16(sb + SM_BH + off, gh + off);
                CP_ASYNC16(sb + SM_BL + off, gl + off);
            }
            CP_COMMIT;
        }
        CP_WAIT0;
        __syncthreads();

        // skip warps with no row in this segment
        bool okA = (segLoRow == s);
        bool okB = (segHiRow == s);
        if (__ballot_sync(0xffffffffu, okA || okB) == 0u) continue;

        // ---- compute: 4 ksteps x (A frag reload + 8 ntiles x 3 mma) ----
        float acc[8][4];
        #pragma unroll
        for (int nt = 0; nt < 8; ++nt)
            #pragma unroll
            for (int q = 0; q < 4; ++q) acc[nt][q] = 0.f;

        #pragma unroll
        for (int kk = 0; kk < 4; ++kk) {
            uint32_t asw = sw128(arow * 128 + (uint32_t)(kk * 32) + acolsel);
            uint32_t ah[4], al[4];
            ldsm_x4(ah[0], ah[1], ah[2], ah[3], sb + SM_AH + asw);
            ldsm_x4(al[0], al[1], al[2], al[3], sb + SM_AL + asw);
            uint32_t roff = ((uint32_t)(kk * 16) + brow_in) * 128;
            #pragma unroll
            for (int nt = 0; nt < 8; ++nt) {
                uint32_t sw = sw128(roff + (uint32_t)nt * 16);
                uint32_t bh0, bh1, bl0, bl1;
                ldsm_x2t(bh0, bh1, sb + SM_BH + sw);
                ldsm_x2t(bl0, bl1, sb + SM_BL + sw);
                mma16816(acc[nt], ah, bh0, bh1);
                mma16816(acc[nt], ah, bl0, bl1);
                mma16816(acc[nt], al, bh0, bh1);
            }
        }

        // ---- store rows belonging to segment s ----
        float* orA = out + (size_t)(r0 + rA) * 64 + cb;
        float* orB = out + (size_t)(r0 + rB) * 64 + cb;
        #pragma unroll
        for (int nt = 0; nt < 8; ++nt) {
            if (okA) *(float2*)(orA + nt * 8) = make_float2(acc[nt][0], acc[nt][1]);
            if (okB) *(float2*)(orB + nt * 8) = make_float2(acc[nt][2], acc[nt][3]);
        }
    }
}

extern "C" void kernel_launch(void* const* d_in, const int* in_sizes, int n_in,
                              void* d_out, int out_size) {
    const float* A    = (const float*)d_in[0];
    const float* B    = (const float*)d_in[1];
    const int*   segA = (const int*)d_in[2];
    const int*   segB = (const int*)d_in[3];
    float* out = (float*)d_out;

    const int N = in_sizes[0] / 64;      // 131072
    const int S = in_sizes[3];           // 128

    presplit_B_kernel<<<S, 256>>>(B, segB);
    segmm_hmma_kernel<<<N / 64, 128>>>(A, segA, out);
}